// round 4
// baseline (speedup 1.0000x reference)
#include <cuda_runtime.h>
#include <math.h>

// ---------------------------------------------------------------------------
// MoE FFN, top-2 of 8 experts, d_model=1024, d_hid=4096, T=4096 tokens.
// Sparse-equivalent of the dense reference (combine weight is 0 for 6/8
// experts, so only the top-2 expert outputs are computed).
//
// Pipeline (all launches on default stream, graph-capturable, no allocs):
//   K0 zero counters
//   K1 routing: logits -> top2 -> softmax weights; count per expert
//   K2 prefix:  128-aligned expert segment bases
//   K3 scatter: token -> (row in expert segment) map
//   K4 gemm<0>: u0 = Xg @ W0[e] + b0        -> g_act   (K=1024, N=4096)
//   K5 gemm<1>: act = u0 * silu(Xg@W1+b1)   -> g_act   (in place)
//   K6 gemm<2>: y   = act @ W2[e] + b2      -> g_y     (K=4096, N=1024)
//   K7 combine: out[t] = w0*y[row0] + w1*y[row1]
//
// GEMM microkernel: 128x128 tile, 256 threads, 8 rows x 4 col-pairs each,
// packed fma.rn.f32x2 (Blackwell FFMA2) for 2x fp32 throughput.
// ---------------------------------------------------------------------------

#define T_TOKENS 4096
#define DM 1024
#define DH 4096
#define NE 8
#define NROWS 9216   // 8192 rows + up to 8*128 alignment padding

// ----- scratch (static __device__ globals; zero-initialized at load) -------
__device__ float g_act[(size_t)NROWS * DH];   // 151 MB: u0, then act (in place)
__device__ float g_y[(size_t)NROWS * DM];     // 37.7 MB
__device__ int   g_perm[NROWS];               // row -> token (pad rows stay 0)
__device__ int   g_tokrow[T_TOKENS * 2];      // token,slot -> row
__device__ float g_tokw[T_TOKENS * 2];        // token,slot -> combine weight
__device__ int   g_tokexp[T_TOKENS * 2];      // token,slot -> expert
__device__ int   g_cnt[NE];
__device__ int   g_run[NE];
__device__ int   g_abase[NE + 1];

// ----- f32x2 helpers -------------------------------------------------------
__device__ __forceinline__ unsigned long long pack2(float x, float y) {
    unsigned long long r;
    asm("mov.b64 %0, {%1, %2};" : "=l"(r) : "f"(x), "f"(y));
    return r;
}
__device__ __forceinline__ void fma2(unsigned long long& acc,
                                     unsigned long long a,
                                     unsigned long long b) {
    asm("fma.rn.f32x2 %0, %1, %2, %0;" : "+l"(acc) : "l"(a), "l"(b));
}
__device__ __forceinline__ float lo32(unsigned long long v) {
    return __uint_as_float((unsigned)(v & 0xffffffffu));
}
__device__ __forceinline__ float hi32(unsigned long long v) {
    return __uint_as_float((unsigned)(v >> 32));
}

// ----- K0: zero counters ---------------------------------------------------
__global__ void zero_kernel() {
    int i = threadIdx.x;
    if (i < NE) g_cnt[i] = 0;
}

// ----- K1: routing (one warp per token) ------------------------------------
__global__ void routing_kernel(const float* __restrict__ x,
                               const float* __restrict__ Wg,
                               const float* __restrict__ bg) {
    int warp = (blockIdx.x * blockDim.x + threadIdx.x) >> 5;
    int lane = threadIdx.x & 31;
    if (warp >= T_TOKENS) return;
    const float* xr = x + (size_t)warp * DM;

    float acc[8];
#pragma unroll
    for (int e = 0; e < 8; e++) acc[e] = 0.f;

    for (int d = lane; d < DM; d += 32) {
        float xv = xr[d];
        const float4* wp = (const float4*)(Wg + (size_t)d * 8);
        float4 wa = wp[0];
        float4 wb = wp[1];
        acc[0] += xv * wa.x; acc[1] += xv * wa.y;
        acc[2] += xv * wa.z; acc[3] += xv * wa.w;
        acc[4] += xv * wb.x; acc[5] += xv * wb.y;
        acc[6] += xv * wb.z; acc[7] += xv * wb.w;
    }
#pragma unroll
    for (int e = 0; e < 8; e++) {
        float v = acc[e];
        for (int o = 16; o; o >>= 1) v += __shfl_xor_sync(0xffffffffu, v, o);
        acc[e] = v;
    }
    if (lane == 0) {
        float lg[8];
#pragma unroll
        for (int e = 0; e < 8; e++) lg[e] = acc[e] + bg[e];
        // top-1 (strict > keeps lowest index on ties, matching jax top_k)
        float v0 = lg[0]; int i0 = 0;
#pragma unroll
        for (int e = 1; e < 8; e++) if (lg[e] > v0) { v0 = lg[e]; i0 = e; }
        float v1 = -3.4e38f; int i1 = -1;
#pragma unroll
        for (int e = 0; e < 8; e++)
            if (e != i0 && lg[e] > v1) { v1 = lg[e]; i1 = e; }
        // softmax over (v0 >= v1)
        float e1 = expf(v1 - v0);
        float w0 = 1.f / (1.f + e1);
        float w1 = e1 / (1.f + e1);
        int t = warp;
        g_tokexp[2 * t + 0] = i0;
        g_tokexp[2 * t + 1] = i1;
        g_tokw[2 * t + 0] = w0;
        g_tokw[2 * t + 1] = w1;
        atomicAdd(&g_cnt[i0], 1);
        atomicAdd(&g_cnt[i1], 1);
    }
}

// ----- K2: 128-aligned segment bases ---------------------------------------
__global__ void prefix_kernel() {
    if (threadIdx.x == 0) {
        int s = 0;
        for (int e = 0; e < NE; e++) {
            g_abase[e] = s;
            g_run[e] = s;
            s += (g_cnt[e] + 127) & ~127;
        }
        g_abase[NE] = s;
    }
}

// ----- K3: scatter token -> row --------------------------------------------
__global__ void scatter_kernel() {
    int t = blockIdx.x * blockDim.x + threadIdx.x;
    if (t >= T_TOKENS) return;
#pragma unroll
    for (int k = 0; k < 2; k++) {
        int e = g_tokexp[2 * t + k];
        int pos = atomicAdd(&g_run[e], 1);
        g_perm[pos] = t;
        g_tokrow[2 * t + k] = pos;
    }
}

// ----- grouped GEMM: 128x128 tile, FFMA2 microkernel -----------------------
// MODE 0: u0 = gather(x) @ W0[e] + b0        -> g_act            (K=DM,N=DH)
// MODE 1: g_act = g_act * silu(gather(x)@W1[e]+b1)   (in place)  (K=DM,N=DH)
// MODE 2: g_y = g_act @ W2[e] + b2                               (K=DH,N=DM)
template <int MODE>
__global__ void __launch_bounds__(256, 2)
moe_gemm(const float* __restrict__ X,
         const float* __restrict__ Ball,
         const float* __restrict__ biasall) {
    const int KD = (MODE == 2) ? DH : DM;
    const int NN = (MODE == 2) ? DM : DH;

    const int r0 = blockIdx.y * 128;
    const int total = g_abase[NE];
    if (r0 >= total) return;
    int e = 0;
    while (e < NE - 1 && r0 >= g_abase[e + 1]) e++;
    int vend = g_abase[e] + g_cnt[e] - r0;
    if (vend <= 0) return;
    if (vend > 128) vend = 128;

    const float* B = Ball + (size_t)e * KD * NN;
    const float* bias = biasall + (size_t)e * NN;
    const int n0 = blockIdx.x * 128;

    __shared__ unsigned long long As2[8][128];  // A, duplicated {a,a}
    __shared__ float Bsf[8][128];

    const int tid = threadIdx.x;
    const int tx = tid & 15;    // col-pair group
    const int ty = tid >> 4;    // row group
    // loader mapping
    const int lm = tid >> 1;          // 0..127  (tile row)
    const int lk = (tid & 1) * 4;     // 0 or 4  (k sub-offset)
    const int bk = tid >> 5;          // 0..7
    const int bn = (tid & 31) * 4;    // 0..124

    const float* arow;
    if (MODE == 2) {
        arow = g_act + (size_t)(r0 + lm) * DH;        // pad rows are all-zero
    } else {
        int t = g_perm[r0 + lm];                       // pad rows map to token 0
        arow = X + (size_t)t * DM;
    }

    unsigned long long acc[8][4];
#pragma unroll
    for (int i = 0; i < 8; i++)
#pragma unroll
        for (int j = 0; j < 4; j++) acc[i][j] = 0ull;

    for (int k0 = 0; k0 < KD; k0 += 8) {
        float4 av = *(const float4*)(arow + k0 + lk);
        As2[lk + 0][lm] = pack2(av.x, av.x);
        As2[lk + 1][lm] = pack2(av.y, av.y);
        As2[lk + 2][lm] = pack2(av.z, av.z);
        As2[lk + 3][lm] = pack2(av.w, av.w);
        float4 bv = *(const float4*)(B + (size_t)(k0 + bk) * NN + n0 + bn);
        *(float4*)&Bsf[bk][bn] = bv;
        __syncthreads();

#pragma unroll
        for (int kk = 0; kk < 8; kk++) {
            const unsigned long long* brow =
                (const unsigned long long*)Bsf[kk];
            unsigned long long b2[4], a2[8];
#pragma unroll
            for (int j = 0; j < 4; j++) b2[j] = brow[tx + 16 * j];
#pragma unroll
            for (int i = 0; i < 8; i++) a2[i] = As2[kk][ty + 16 * i];
#pragma unroll
            for (int i = 0; i < 8; i++)
#pragma unroll
                for (int j = 0; j < 4; j++) fma2(acc[i][j], a2[i], b2[j]);
        }
        __syncthreads();
    }

    // epilogue
#pragma unroll
    for (int i = 0; i < 8; i++) {
        int m = ty + 16 * i;
        if (m >= vend) continue;
        size_t r = (size_t)(r0 + m);
#pragma unroll
        for (int j = 0; j < 4; j++) {
            int c0 = n0 + 2 * (tx + 16 * j);
            float f0 = lo32(acc[i][j]) + bias[c0];
            float f1 = hi32(acc[i][j]) + bias[c0 + 1];
            if (MODE == 0) {
                g_act[r * DH + c0] = f0;
                g_act[r * DH + c0 + 1] = f1;
            } else if (MODE == 1) {
                float h0 = g_act[r * DH + c0];
                float h1 = g_act[r * DH + c0 + 1];
                float s0 = f0 / (1.f + expf(-f0));
                float s1 = f1 / (1.f + expf(-f1));
                g_act[r * DH + c0] = h0 * s0;
                g_act[r * DH + c0 + 1] = h1 * s1;
            } else {
                g_y[r * DM + c0] = f0;
                g_y[r * DM + c0 + 1] = f1;
            }
        }
    }
}

// ----- K7: combine ---------------------------------------------------------
__global__ void combine_kernel(float* __restrict__ out) {
    int t = blockIdx.x;
    int d4 = threadIdx.x;  // 256 threads x float4 = 1024
    int r0 = g_tokrow[2 * t + 0];
    int r1 = g_tokrow[2 * t + 1];
    float w0 = g_tokw[2 * t + 0];
    float w1 = g_tokw[2 * t + 1];
    const float4 y0 = *(const float4*)(g_y + (size_t)r0 * DM + d4 * 4);
    const float4 y1 = *(const float4*)(g_y + (size_t)r1 * DM + d4 * 4);
    float4 o;
    o.x = w0 * y0.x + w1 * y1.x;
    o.y = w0 * y0.y + w1 * y1.y;
    o.z = w0 * y0.z + w1 * y1.z;
    o.w = w0 * y0.w + w1 * y1.w;
    *(float4*)(out + (size_t)t * DM + d4 * 4) = o;
}

// ---------------------------------------------------------------------------
extern "C" void kernel_launch(void* const* d_in, const int* in_sizes, int n_in,
                              void* d_out, int out_size) {
    (void)in_sizes; (void)n_in; (void)out_size;
    const float* x  = (const float*)d_in[0];
    const float* Wg = (const float*)d_in[1];
    const float* bg = (const float*)d_in[2];
    const float* W0 = (const float*)d_in[3];
    const float* b0 = (const float*)d_in[4];
    const float* W1 = (const float*)d_in[5];
    const float* b1 = (const float*)d_in[6];
    const float* W2 = (const float*)d_in[7];
    const float* b2 = (const float*)d_in[8];
    float* out = (float*)d_out;

    zero_kernel<<<1, 32>>>();
    routing_kernel<<<T_TOKENS / 8, 256>>>(x, Wg, bg);
    prefix_kernel<<<1, 32>>>();
    scatter_kernel<<<T_TOKENS / 256, 256>>>();

    dim3 blk(256);
    dim3 g01(DH / 128, NROWS / 128);  // (32, 72)
    dim3 g2(DM / 128, NROWS / 128);   // (8, 72)
    moe_gemm<0><<<g01, blk>>>(x, W0, b0);
    moe_gemm<1><<<g01, blk>>>(x, W1, b1);
    moe_gemm<2><<<g2, blk>>>(x, W2, b2);

    combine_kernel<<<T_TOKENS, 256>>>(out);
}

// round 6
// speedup vs baseline: 2.1369x; 2.1369x over previous
#include <cuda_runtime.h>
#include <cuda_bf16.h>
#include <math.h>
#include <stdint.h>

// ---------------------------------------------------------------------------
// MoE FFN (top-2 of 8, d_model=1024, d_hid=4096, T=4096).
// Tensor-core path via mma.sync.m16n8k16 (bf16, fp32 acc) — base sm_103
// PTX target safe (no tcgen05 / 'a'-gated features).
//
//   zero / routing / prefix / scatter
//   transpose_convert x3: W fp32 [E][K][N] -> bf16 hi/lo [E][N][K]
//   moe_gemm_mma<0>: u0 = Xg @ W0 + b0
//   moe_gemm_mma<1>: act = u0 * silu(Xg@W1+b1)
//   moe_gemm_mma<2>: y   = act @ W2 + b2
//   combine
//
// 3-term bf16 split (hi*hi + hi*lo + lo*hi) for fp32-grade accuracy.
// CTA tile 128x128, BK=32, 8 warps (2M x 4N), warp tile 64x32,
// double-buffered smem, 80B row stride (16B-aligned, LDSM conflict-free).
// ---------------------------------------------------------------------------

#define T_TOKENS 4096
#define DM 1024
#define DH 4096
#define NE 8
#define NROWS 9216

// ----- scratch -------------------------------------------------------------
__device__ float g_act[(size_t)NROWS * DH];
__device__ float g_y[(size_t)NROWS * DM];
__device__ int   g_perm[NROWS];
__device__ int   g_tokrow[T_TOKENS * 2];
__device__ float g_tokw[T_TOKENS * 2];
__device__ int   g_tokexp[T_TOKENS * 2];
__device__ int   g_cnt[NE];
__device__ int   g_run[NE];
__device__ int   g_abase[NE + 1];

__device__ __nv_bfloat16 g_w0h[(size_t)NE * DH * DM];
__device__ __nv_bfloat16 g_w0l[(size_t)NE * DH * DM];
__device__ __nv_bfloat16 g_w1h[(size_t)NE * DH * DM];
__device__ __nv_bfloat16 g_w1l[(size_t)NE * DH * DM];
__device__ __nv_bfloat16 g_w2h[(size_t)NE * DM * DH];
__device__ __nv_bfloat16 g_w2l[(size_t)NE * DM * DH];

// ----- helpers -------------------------------------------------------------
__device__ __forceinline__ uint32_t s2u(const void* p) {
    uint32_t a;
    asm("{ .reg .u64 t; cvta.to.shared.u64 t, %1; cvt.u32.u64 %0, t; }"
        : "=r"(a) : "l"(p));
    return a;
}
// f -> bf16 hi (truncate) + bf16 lo (RN of residual), two floats packed
__device__ __forceinline__ void cvt2(float f0, float f1, uint32_t& hi2, uint32_t& lo2) {
    uint32_t u0 = __float_as_uint(f0), u1 = __float_as_uint(f1);
    hi2 = (u0 >> 16) | (u1 & 0xffff0000u);
    float r0 = f0 - __uint_as_float(u0 & 0xffff0000u);
    float r1 = f1 - __uint_as_float(u1 & 0xffff0000u);
    asm("cvt.rn.bf16x2.f32 %0, %1, %2;" : "=r"(lo2) : "f"(r1), "f"(r0));
}
__device__ __forceinline__ void ldsm4(uint32_t* r, uint32_t addr) {
    asm volatile("ldmatrix.sync.aligned.m8n8.x4.shared.b16 {%0,%1,%2,%3}, [%4];"
                 : "=r"(r[0]), "=r"(r[1]), "=r"(r[2]), "=r"(r[3]) : "r"(addr));
}
__device__ __forceinline__ void mma16816(float* c, const uint32_t* a,
                                         uint32_t b0, uint32_t b1) {
    asm volatile(
        "mma.sync.aligned.m16n8k16.row.col.f32.bf16.bf16.f32 "
        "{%0,%1,%2,%3}, {%4,%5,%6,%7}, {%8,%9}, {%0,%1,%2,%3};"
        : "+f"(c[0]), "+f"(c[1]), "+f"(c[2]), "+f"(c[3])
        : "r"(a[0]), "r"(a[1]), "r"(a[2]), "r"(a[3]), "r"(b0), "r"(b1));
}

// ----- K0: zero counters ---------------------------------------------------
__global__ void zero_kernel() {
    int i = threadIdx.x;
    if (i < NE) g_cnt[i] = 0;
}

// ----- K1: routing (one warp per token) ------------------------------------
__global__ void routing_kernel(const float* __restrict__ x,
                               const float* __restrict__ Wg,
                               const float* __restrict__ bg) {
    int warp = (blockIdx.x * blockDim.x + threadIdx.x) >> 5;
    int lane = threadIdx.x & 31;
    if (warp >= T_TOKENS) return;
    const float* xr = x + (size_t)warp * DM;

    float acc[8];
#pragma unroll
    for (int e = 0; e < 8; e++) acc[e] = 0.f;
    for (int d = lane; d < DM; d += 32) {
        float xv = xr[d];
        const float4* wp = (const float4*)(Wg + (size_t)d * 8);
        float4 wa = wp[0];
        float4 wb = wp[1];
        acc[0] += xv * wa.x; acc[1] += xv * wa.y;
        acc[2] += xv * wa.z; acc[3] += xv * wa.w;
        acc[4] += xv * wb.x; acc[5] += xv * wb.y;
        acc[6] += xv * wb.z; acc[7] += xv * wb.w;
    }
#pragma unroll
    for (int e = 0; e < 8; e++) {
        float v = acc[e];
        for (int o = 16; o; o >>= 1) v += __shfl_xor_sync(0xffffffffu, v, o);
        acc[e] = v;
    }
    if (lane == 0) {
        float lg[8];
#pragma unroll
        for (int e = 0; e < 8; e++) lg[e] = acc[e] + bg[e];
        float v0 = lg[0]; int i0 = 0;
#pragma unroll
        for (int e = 1; e < 8; e++) if (lg[e] > v0) { v0 = lg[e]; i0 = e; }
        float v1 = -3.4e38f; int i1 = -1;
#pragma unroll
        for (int e = 0; e < 8; e++)
            if (e != i0 && lg[e] > v1) { v1 = lg[e]; i1 = e; }
        float e1 = expf(v1 - v0);
        float w0 = 1.f / (1.f + e1);
        float w1 = e1 / (1.f + e1);
        int t = warp;
        g_tokexp[2 * t + 0] = i0;
        g_tokexp[2 * t + 1] = i1;
        g_tokw[2 * t + 0] = w0;
        g_tokw[2 * t + 1] = w1;
        atomicAdd(&g_cnt[i0], 1);
        atomicAdd(&g_cnt[i1], 1);
    }
}

// ----- K2: 128-aligned segment bases ---------------------------------------
__global__ void prefix_kernel() {
    if (threadIdx.x == 0) {
        int s = 0;
        for (int e = 0; e < NE; e++) {
            g_abase[e] = s;
            g_run[e] = s;
            s += (g_cnt[e] + 127) & ~127;
        }
        g_abase[NE] = s;
    }
}

// ----- K3: scatter token -> row --------------------------------------------
__global__ void scatter_kernel() {
    int t = blockIdx.x * blockDim.x + threadIdx.x;
    if (t >= T_TOKENS) return;
#pragma unroll
    for (int k = 0; k < 2; k++) {
        int e = g_tokexp[2 * t + k];
        int pos = atomicAdd(&g_run[e], 1);
        g_perm[pos] = t;
        g_tokrow[2 * t + k] = pos;
    }
}

// ----- transpose + split-convert W[e][K][N] fp32 -> [e][N][K] bf16 hi/lo ---
template <int WHICH>
__global__ void transpose_convert(const float* __restrict__ W) {
    const int K = (WHICH == 2) ? DH : DM;
    const int N = (WHICH == 2) ? DM : DH;
    __nv_bfloat16* oh = (WHICH == 0) ? g_w0h : (WHICH == 1) ? g_w1h : g_w2h;
    __nv_bfloat16* ol = (WHICH == 0) ? g_w0l : (WHICH == 1) ? g_w1l : g_w2l;
    __shared__ float tile[32][33];
    int e = blockIdx.z;
    int n0 = blockIdx.x * 32, k0 = blockIdx.y * 32;
    int tx = threadIdx.x, ty = threadIdx.y;  // 32 x 8
    const float* src = W + ((size_t)e * K + k0) * N + n0 + tx;
#pragma unroll
    for (int i = 0; i < 4; i++)
        tile[ty + 8 * i][tx] = src[(size_t)(ty + 8 * i) * N];
    __syncthreads();
    size_t ob = ((size_t)e * N + n0) * K + k0 + tx;
#pragma unroll
    for (int i = 0; i < 4; i++) {
        int nl = ty + 8 * i;
        float f = tile[tx][nl];
        uint32_t u = __float_as_uint(f);
        oh[ob + (size_t)nl * K] = __ushort_as_bfloat16((unsigned short)(u >> 16));
        float lo = f - __uint_as_float(u & 0xffff0000u);
        ol[ob + (size_t)nl * K] = __float2bfloat16_rn(lo);
    }
}

// ----- HMMA grouped GEMM ---------------------------------------------------
// Smem stage (40960 B): Ahi[0) Alo[10240) Bhi[20480) Blo[30720); 80B row pitch.
#define STG_BYTES 40960
#define PITCH 80
#define SMEM_DYN (2 * STG_BYTES)

template <int MODE>
__global__ void __launch_bounds__(256, 1)
moe_gemm_mma(const float* __restrict__ X, const float* __restrict__ biasall) {
    const int KD = (MODE == 2) ? DH : DM;
    const int NN = (MODE == 2) ? DM : DH;

    const int r0 = blockIdx.y * 128;
    if (r0 >= g_abase[NE]) return;
    int e = 0;
    while (e < NE - 1 && r0 >= g_abase[e + 1]) e++;
    int vend = g_abase[e] + g_cnt[e] - r0;
    if (vend <= 0) return;
    if (vend > 128) vend = 128;
    const int n0 = blockIdx.x * 128;

    extern __shared__ char smem_raw[];
    const uint32_t sb = s2u(smem_raw);

    const int tid = threadIdx.x;
    const int w = tid >> 5;
    const int lane = tid & 31;
    const int wm = w & 1;        // M half: 0/1 -> rows 0-63 / 64-127
    const int wn = w >> 1;       // N quarter: cols wn*32

    // ---- gmem load mapping (per stage: A 128x32 fp32, B 128x32 bf16 hi+lo)
    const int arow_i = tid >> 1;
    const int ahalf = (tid & 1) * 16;  // k sub-offset (elements)
    const float* aptr;
    if (MODE == 2) {
        aptr = g_act + (size_t)(r0 + arow_i) * DH + ahalf;
    } else {
        aptr = X + (size_t)g_perm[r0 + arow_i] * DM + ahalf;
    }
    const __nv_bfloat16* Bh = (MODE == 0) ? g_w0h : (MODE == 1) ? g_w1h : g_w2h;
    const __nv_bfloat16* Bl = (MODE == 0) ? g_w0l : (MODE == 1) ? g_w1l : g_w2l;
    const __nv_bfloat16* bhptr = Bh + ((size_t)e * NN + n0 + arow_i) * KD + ahalf;
    const __nv_bfloat16* blptr = Bl + ((size_t)e * NN + n0 + arow_i) * KD + ahalf;

    const uint32_t stoff = (uint32_t)(arow_i * PITCH + (tid & 1) * 32);

    // ---- ldmatrix address offsets (within a stage buffer)
    // A m16k16 frag: row = wm*64 + mf*16 + (lane&15), col8 = (lane>>4)*8
    const uint32_t a_ld = (uint32_t)((wm * 64 + (lane & 15)) * PITCH +
                                     ((lane >> 4) * 8) * 2);
    // B k16n16 (x4 = two n8 frags): row = wn*32 + p*16 + (lane&7) + ((lane>>4)&1)*8
    //                               col8 = ((lane>>3)&1)*8
    const uint32_t b_ld = (uint32_t)((wn * 32 + (lane & 7) + ((lane >> 4) & 1) * 8) * PITCH +
                                     (((lane >> 3) & 1) * 8) * 2);

    float acc[4][4][4];
#pragma unroll
    for (int i = 0; i < 4; i++)
#pragma unroll
        for (int j = 0; j < 4; j++)
#pragma unroll
            for (int q = 0; q < 4; q++) acc[i][j][q] = 0.f;

    float4 pa[4];
    uint4 pbh[2], pbl[2];

    auto ldg = [&](int k0) {
#pragma unroll
        for (int i = 0; i < 4; i++) pa[i] = *(const float4*)(aptr + k0 + 4 * i);
        pbh[0] = *(const uint4*)(bhptr + k0);
        pbh[1] = *(const uint4*)(bhptr + k0 + 8);
        pbl[0] = *(const uint4*)(blptr + k0);
        pbl[1] = *(const uint4*)(blptr + k0 + 8);
    };
    auto sts = [&](uint32_t bb) {
        uint32_t h[8], l[8];
#pragma unroll
        for (int i = 0; i < 4; i++)
            cvt2(pa[i].x, pa[i].y, h[2 * i], l[2 * i]),
            cvt2(pa[i].z, pa[i].w, h[2 * i + 1], l[2 * i + 1]);
        // interleave: h[0],h[2]? no: pairs are sequential k: h[0]=(k0,k1) h[1]=(k2,k3)...
        uint32_t a0 = bb + stoff;
        asm volatile("st.shared.v4.b32 [%0], {%1,%2,%3,%4};"
                     :: "r"(a0), "r"(h[0]), "r"(h[1]), "r"(h[2]), "r"(h[3]) : "memory");
        asm volatile("st.shared.v4.b32 [%0], {%1,%2,%3,%4};"
                     :: "r"(a0 + 16), "r"(h[4]), "r"(h[5]), "r"(h[6]), "r"(h[7]) : "memory");
        asm volatile("st.shared.v4.b32 [%0], {%1,%2,%3,%4};"
                     :: "r"(a0 + 10240), "r"(l[0]), "r"(l[1]), "r"(l[2]), "r"(l[3]) : "memory");
        asm volatile("st.shared.v4.b32 [%0], {%1,%2,%3,%4};"
                     :: "r"(a0 + 10256), "r"(l[4]), "r"(l[5]), "r"(l[6]), "r"(l[7]) : "memory");
        asm volatile("st.shared.v4.b32 [%0], {%1,%2,%3,%4};"
                     :: "r"(a0 + 20480), "r"(pbh[0].x), "r"(pbh[0].y), "r"(pbh[0].z), "r"(pbh[0].w) : "memory");
        asm volatile("st.shared.v4.b32 [%0], {%1,%2,%3,%4};"
                     :: "r"(a0 + 20496), "r"(pbh[1].x), "r"(pbh[1].y), "r"(pbh[1].z), "r"(pbh[1].w) : "memory");
        asm volatile("st.shared.v4.b32 [%0], {%1,%2,%3,%4};"
                     :: "r"(a0 + 30720), "r"(pbl[0].x), "r"(pbl[0].y), "r"(pbl[0].z), "r"(pbl[0].w) : "memory");
        asm volatile("st.shared.v4.b32 [%0], {%1,%2,%3,%4};"
                     :: "r"(a0 + 30736), "r"(pbl[1].x), "r"(pbl[1].y), "r"(pbl[1].z), "r"(pbl[1].w) : "memory");
    };

    const int S = KD / 32;

    ldg(0);
    sts(sb);
    __syncthreads();

    for (int s = 0; s < S; s++) {
        if (s + 1 < S) ldg((s + 1) * 32);
        const uint32_t bb = sb + (uint32_t)(s & 1) * STG_BYTES;
#pragma unroll
        for (int ks = 0; ks < 2; ks++) {
            const uint32_t ko = (uint32_t)(ks * 32);
            uint32_t ah[4][4], al[4][4], bh[2][4], bl[2][4];
#pragma unroll
            for (int mf = 0; mf < 4; mf++) {
                ldsm4(ah[mf], bb + a_ld + (uint32_t)(mf * 16 * PITCH) + ko);
                ldsm4(al[mf], bb + 10240 + a_ld + (uint32_t)(mf * 16 * PITCH) + ko);
            }
#pragma unroll
            for (int p = 0; p < 2; p++) {
                ldsm4(bh[p], bb + 20480 + b_ld + (uint32_t)(p * 16 * PITCH) + ko);
                ldsm4(bl[p], bb + 30720 + b_ld + (uint32_t)(p * 16 * PITCH) + ko);
            }
#pragma unroll
            for (int mf = 0; mf < 4; mf++)
#pragma unroll
                for (int p = 0; p < 2; p++)
#pragma unroll
                    for (int sub = 0; sub < 2; sub++) {
                        int nf = p * 2 + sub;
                        mma16816(acc[mf][nf], ah[mf], bh[p][2 * sub], bh[p][2 * sub + 1]);
                        mma16816(acc[mf][nf], ah[mf], bl[p][2 * sub], bl[p][2 * sub + 1]);
                        mma16816(acc[mf][nf], al[mf], bh[p][2 * sub], bh[p][2 * sub + 1]);
                    }
        }
        if (s + 1 < S) sts(sb + (uint32_t)((s + 1) & 1) * STG_BYTES);
        __syncthreads();
    }

    // ---- epilogue -----------------------------------------------------------
    const float* bias = biasall + (size_t)e * NN + n0;
#pragma unroll
    for (int mf = 0; mf < 4; mf++) {
        int mbase = wm * 64 + mf * 16 + (lane >> 2);
#pragma unroll
        for (int half = 0; half < 2; half++) {
            int m = mbase + half * 8;
            if (m >= vend) continue;
            size_t r = (size_t)(r0 + m);
#pragma unroll
            for (int nf = 0; nf < 4; nf++) {
                int col = wn * 32 + nf * 8 + (lane & 3) * 2;
                float c0 = acc[mf][nf][2 * half + 0] + bias[col];
                float c1 = acc[mf][nf][2 * half + 1] + bias[col + 1];
                if (MODE == 2) {
                    float2* dst = (float2*)(g_y + r * DM + n0 + col);
                    *dst = make_float2(c0, c1);
                } else if (MODE == 0) {
                    float2* dst = (float2*)(g_act + r * DH + n0 + col);
                    *dst = make_float2(c0, c1);
                } else {
                    float2* dst = (float2*)(g_act + r * DH + n0 + col);
                    float2 h = *dst;
                    float s0 = c0 / (1.f + expf(-c0));
                    float s1 = c1 / (1.f + expf(-c1));
                    *dst = make_float2(h.x * s0, h.y * s1);
                }
            }
        }
    }
}

// ----- combine -------------------------------------------------------------
__global__ void combine_kernel(float* __restrict__ out) {
    int t = blockIdx.x;
    int d4 = threadIdx.x;
    int r0 = g_tokrow[2 * t + 0];
    int r1 = g_tokrow[2 * t + 1];
    float w0 = g_tokw[2 * t + 0];
    float w1 = g_tokw[2 * t + 1];
    const float4 y0 = *(const float4*)(g_y + (size_t)r0 * DM + d4 * 4);
    const float4 y1 = *(const float4*)(g_y + (size_t)r1 * DM + d4 * 4);
    float4 o;
    o.x = w0 * y0.x + w1 * y1.x;
    o.y = w0 * y0.y + w1 * y1.y;
    o.z = w0 * y0.z + w1 * y1.z;
    o.w = w0 * y0.w + w1 * y1.w;
    *(float4*)(out + (size_t)t * DM + d4 * 4) = o;
}

// ---------------------------------------------------------------------------
extern "C" void kernel_launch(void* const* d_in, const int* in_sizes, int n_in,
                              void* d_out, int out_size) {
    (void)in_sizes; (void)n_in; (void)out_size;
    const float* x  = (const float*)d_in[0];
    const float* Wg = (const float*)d_in[1];
    const float* bg = (const float*)d_in[2];
    const float* W0 = (const float*)d_in[3];
    const float* b0 = (const float*)d_in[4];
    const float* W1 = (const float*)d_in[5];
    const float* b1 = (const float*)d_in[6];
    const float* W2 = (const float*)d_in[7];
    const float* b2 = (const float*)d_in[8];
    float* out = (float*)d_out;

    cudaFuncSetAttribute(moe_gemm_mma<0>,
                         cudaFuncAttributeMaxDynamicSharedMemorySize, SMEM_DYN);
    cudaFuncSetAttribute(moe_gemm_mma<1>,
                         cudaFuncAttributeMaxDynamicSharedMemorySize, SMEM_DYN);
    cudaFuncSetAttribute(moe_gemm_mma<2>,
                         cudaFuncAttributeMaxDynamicSharedMemorySize, SMEM_DYN);

    zero_kernel<<<1, 32>>>();
    routing_kernel<<<T_TOKENS / 8, 256>>>(x, Wg, bg);
    prefix_kernel<<<1, 32>>>();
    scatter_kernel<<<T_TOKENS / 256, 256>>>();

    dim3 tb(32, 8);
    transpose_convert<0><<<dim3(DH / 32, DM / 32, NE), tb>>>(W0);
    transpose_convert<1><<<dim3(DH / 32, DM / 32, NE), tb>>>(W1);
    transpose_convert<2><<<dim3(DM / 32, DH / 32, NE), tb>>>(W2);

    moe_gemm_mma<0><<<dim3(DH / 128, NROWS / 128), 256, SMEM_DYN>>>(x, b0);
    moe_gemm_mma<1><<<dim3(DH / 128, NROWS / 128), 256, SMEM_DYN>>>(x, b1);
    moe_gemm_mma<2><<<dim3(DM / 128, NROWS / 128), 256, SMEM_DYN>>>(nullptr, b2);

    combine_kernel<<<T_TOKENS, 256>>>(out);
}

// round 7
// speedup vs baseline: 2.3121x; 1.0820x over previous
#include <cuda_runtime.h>
#include <cuda_bf16.h>
#include <math.h>
#include <stdint.h>

// ---------------------------------------------------------------------------
// MoE FFN (top-2 of 8, d_model=1024, d_hid=4096, T=4096), mma.sync bf16 path.
//
//   convert_x (+zero): x fp32 -> g_xh/g_xl bf16 hi/lo
//   transpose_convert x3: W fp32 [E][K][N] -> bf16 hi/lo [E][N][K]
//   routing / prefix / scatter
//   moe_gemm<0>: u0 = Xg @ W0 + b0          (fp32 out)
//   moe_gemm<1>: act = u0 * silu(Xg@W1+b1)  (bf16 hi/lo out)
//   moe_gemm<2>: y   = act @ W2 + b2
//   combine
//
// GEMM: all operands preconverted bf16; mainloop is pure cp.async (3-stage
// ring, one syncthreads/stage) + ldmatrix + 3-term-split HMMA (fp32 acc).
// CTA tile 128x128, BK=32, 8 warps (2Mx4N), 80B smem pitch.
// ---------------------------------------------------------------------------

#define T_TOKENS 4096
#define DM 1024
#define DH 4096
#define NE 8
#define NROWS 9216

// ----- scratch -------------------------------------------------------------
__device__ float g_act[(size_t)NROWS * DH];        // u0 (fp32, gemm0 -> gemm1)
__device__ __nv_bfloat16 g_acth[(size_t)NROWS * DH];  // act hi (gemm1 -> gemm2)
__device__ __nv_bfloat16 g_actl[(size_t)NROWS * DH];  // act lo
__device__ float g_y[(size_t)NROWS * DM];
__device__ __nv_bfloat16 g_xh[(size_t)T_TOKENS * DM];
__device__ __nv_bfloat16 g_xl[(size_t)T_TOKENS * DM];
__device__ int   g_perm[NROWS];
__device__ int   g_tokrow[T_TOKENS * 2];
__device__ float g_tokw[T_TOKENS * 2];
__device__ int   g_tokexp[T_TOKENS * 2];
__device__ int   g_cnt[NE];
__device__ int   g_run[NE];
__device__ int   g_abase[NE + 1];

__device__ __nv_bfloat16 g_w0h[(size_t)NE * DH * DM];
__device__ __nv_bfloat16 g_w0l[(size_t)NE * DH * DM];
__device__ __nv_bfloat16 g_w1h[(size_t)NE * DH * DM];
__device__ __nv_bfloat16 g_w1l[(size_t)NE * DH * DM];
__device__ __nv_bfloat16 g_w2h[(size_t)NE * DM * DH];
__device__ __nv_bfloat16 g_w2l[(size_t)NE * DM * DH];

// ----- helpers -------------------------------------------------------------
__device__ __forceinline__ uint32_t s2u(const void* p) {
    uint32_t a;
    asm("{ .reg .u64 t; cvta.to.shared.u64 t, %1; cvt.u32.u64 %0, t; }"
        : "=r"(a) : "l"(p));
    return a;
}
__device__ __forceinline__ void cvt2(float f0, float f1, uint32_t& hi2, uint32_t& lo2) {
    uint32_t u0 = __float_as_uint(f0), u1 = __float_as_uint(f1);
    hi2 = (u0 >> 16) | (u1 & 0xffff0000u);
    float r0 = f0 - __uint_as_float(u0 & 0xffff0000u);
    float r1 = f1 - __uint_as_float(u1 & 0xffff0000u);
    asm("cvt.rn.bf16x2.f32 %0, %1, %2;" : "=r"(lo2) : "f"(r1), "f"(r0));
}
__device__ __forceinline__ void ldsm4(uint32_t* r, uint32_t addr) {
    asm volatile("ldmatrix.sync.aligned.m8n8.x4.shared.b16 {%0,%1,%2,%3}, [%4];"
                 : "=r"(r[0]), "=r"(r[1]), "=r"(r[2]), "=r"(r[3]) : "r"(addr));
}
__device__ __forceinline__ void mma16816(float* c, const uint32_t* a,
                                         uint32_t b0, uint32_t b1) {
    asm volatile(
        "mma.sync.aligned.m16n8k16.row.col.f32.bf16.bf16.f32 "
        "{%0,%1,%2,%3}, {%4,%5,%6,%7}, {%8,%9}, {%0,%1,%2,%3};"
        : "+f"(c[0]), "+f"(c[1]), "+f"(c[2]), "+f"(c[3])
        : "r"(a[0]), "r"(a[1]), "r"(a[2]), "r"(a[3]), "r"(b0), "r"(b1));
}
__device__ __forceinline__ void cpa16(uint32_t d, const void* g) {
    asm volatile("cp.async.cg.shared.global [%0], [%1], 16;" :: "r"(d), "l"(g));
}
__device__ __forceinline__ void cpa_commit() {
    asm volatile("cp.async.commit_group;" ::: "memory");
}
__device__ __forceinline__ void cpa_wait1() {
    asm volatile("cp.async.wait_group 1;" ::: "memory");
}

// ----- convert_x (+ counter zero) ------------------------------------------
__global__ void convert_x_kernel(const float* __restrict__ x) {
    if (blockIdx.x == 0 && threadIdx.x < NE) g_cnt[threadIdx.x] = 0;
    size_t i = ((size_t)blockIdx.x * blockDim.x + threadIdx.x) * 4;
    if (i >= (size_t)T_TOKENS * DM) return;
    float4 v = *(const float4*)(x + i);
    uint32_t h0, l0, h1, l1;
    cvt2(v.x, v.y, h0, l0);
    cvt2(v.z, v.w, h1, l1);
    uint2* ph = (uint2*)(g_xh + i);
    uint2* pl = (uint2*)(g_xl + i);
    *ph = make_uint2(h0, h1);
    *pl = make_uint2(l0, l1);
}

// ----- routing (one warp per token) ----------------------------------------
__global__ void routing_kernel(const float* __restrict__ x,
                               const float* __restrict__ Wg,
                               const float* __restrict__ bg) {
    int warp = (blockIdx.x * blockDim.x + threadIdx.x) >> 5;
    int lane = threadIdx.x & 31;
    if (warp >= T_TOKENS) return;
    const float* xr = x + (size_t)warp * DM;

    float acc[8];
#pragma unroll
    for (int e = 0; e < 8; e++) acc[e] = 0.f;
    for (int d = lane; d < DM; d += 32) {
        float xv = xr[d];
        const float4* wp = (const float4*)(Wg + (size_t)d * 8);
        float4 wa = wp[0];
        float4 wb = wp[1];
        acc[0] += xv * wa.x; acc[1] += xv * wa.y;
        acc[2] += xv * wa.z; acc[3] += xv * wa.w;
        acc[4] += xv * wb.x; acc[5] += xv * wb.y;
        acc[6] += xv * wb.z; acc[7] += xv * wb.w;
    }
#pragma unroll
    for (int e = 0; e < 8; e++) {
        float v = acc[e];
        for (int o = 16; o; o >>= 1) v += __shfl_xor_sync(0xffffffffu, v, o);
        acc[e] = v;
    }
    if (lane == 0) {
        float lg[8];
#pragma unroll
        for (int e = 0; e < 8; e++) lg[e] = acc[e] + bg[e];
        float v0 = lg[0]; int i0 = 0;
#pragma unroll
        for (int e = 1; e < 8; e++) if (lg[e] > v0) { v0 = lg[e]; i0 = e; }
        float v1 = -3.4e38f; int i1 = -1;
#pragma unroll
        for (int e = 0; e < 8; e++)
            if (e != i0 && lg[e] > v1) { v1 = lg[e]; i1 = e; }
        float e1 = expf(v1 - v0);
        float w0 = 1.f / (1.f + e1);
        float w1 = e1 / (1.f + e1);
        int t = warp;
        g_tokexp[2 * t + 0] = i0;
        g_tokexp[2 * t + 1] = i1;
        g_tokw[2 * t + 0] = w0;
        g_tokw[2 * t + 1] = w1;
        atomicAdd(&g_cnt[i0], 1);
        atomicAdd(&g_cnt[i1], 1);
    }
}

// ----- prefix / scatter ----------------------------------------------------
__global__ void prefix_kernel() {
    if (threadIdx.x == 0) {
        int s = 0;
        for (int e = 0; e < NE; e++) {
            g_abase[e] = s;
            g_run[e] = s;
            s += (g_cnt[e] + 127) & ~127;
        }
        g_abase[NE] = s;
    }
}
__global__ void scatter_kernel() {
    int t = blockIdx.x * blockDim.x + threadIdx.x;
    if (t >= T_TOKENS) return;
#pragma unroll
    for (int k = 0; k < 2; k++) {
        int e = g_tokexp[2 * t + k];
        int pos = atomicAdd(&g_run[e], 1);
        g_perm[pos] = t;
        g_tokrow[2 * t + k] = pos;
    }
}

// ----- transpose + split-convert W[e][K][N] fp32 -> [e][N][K] bf16 hi/lo ---
template <int WHICH>
__global__ void transpose_convert(const float* __restrict__ W) {
    const int K = (WHICH == 2) ? DH : DM;
    const int N = (WHICH == 2) ? DM : DH;
    __nv_bfloat16* oh = (WHICH == 0) ? g_w0h : (WHICH == 1) ? g_w1h : g_w2h;
    __nv_bfloat16* ol = (WHICH == 0) ? g_w0l : (WHICH == 1) ? g_w1l : g_w2l;
    __shared__ float tile[32][33];
    int e = blockIdx.z;
    int n0 = blockIdx.x * 32, k0 = blockIdx.y * 32;
    int tx = threadIdx.x, ty = threadIdx.y;  // 32 x 8
    const float* src = W + ((size_t)e * K + k0) * N + n0 + tx;
#pragma unroll
    for (int i = 0; i < 4; i++)
        tile[ty + 8 * i][tx] = src[(size_t)(ty + 8 * i) * N];
    __syncthreads();
    size_t ob = ((size_t)e * N + n0) * K + k0 + tx;
#pragma unroll
    for (int i = 0; i < 4; i++) {
        int nl = ty + 8 * i;
        float f = tile[tx][nl];
        uint32_t u = __float_as_uint(f);
        oh[ob + (size_t)nl * K] = __ushort_as_bfloat16((unsigned short)(u >> 16));
        float lo = f - __uint_as_float(u & 0xffff0000u);
        ol[ob + (size_t)nl * K] = __float2bfloat16_rn(lo);
    }
}

// ----- HMMA grouped GEMM (cp.async 3-stage ring) ---------------------------
// Stage (40960 B): Ahi[0) Alo[10240) Bhi[20480) Blo[30720); 80 B row pitch.
#define STG_BYTES 40960
#define PITCH 80
#define SMEM_DYN (3 * STG_BYTES)

template <int MODE>
__global__ void __launch_bounds__(256, 1)
moe_gemm_mma(const float* __restrict__ biasall) {
    const int KD = (MODE == 2) ? DH : DM;
    const int NN = (MODE == 2) ? DM : DH;

    const int r0 = blockIdx.y * 128;
    if (r0 >= g_abase[NE]) return;
    int e = 0;
    while (e < NE - 1 && r0 >= g_abase[e + 1]) e++;
    int vend = g_abase[e] + g_cnt[e] - r0;
    if (vend <= 0) return;
    if (vend > 128) vend = 128;
    const int n0 = blockIdx.x * 128;

    extern __shared__ char smem_raw[];
    const uint32_t sb = s2u(smem_raw);

    const int tid = threadIdx.x;
    const int w = tid >> 5;
    const int lane = tid & 31;
    const int wm = w & 1;
    const int wn = w >> 1;

    // ---- cp.async mapping: thread owns one tile row, half (32B) of stage k
    const int row_i = tid >> 1;
    const int coff = (tid & 1) * 32;  // byte offset within 64B row-stage
    const char* agh;
    const char* agl;
    if (MODE == 2) {
        agh = (const char*)(g_acth + (size_t)(r0 + row_i) * DH) + coff;
        agl = (const char*)(g_actl + (size_t)(r0 + row_i) * DH) + coff;
    } else {
        size_t t = (size_t)g_perm[r0 + row_i];
        agh = (const char*)(g_xh + t * DM) + coff;
        agl = (const char*)(g_xl + t * DM) + coff;
    }
    const __nv_bfloat16* Bh = (MODE == 0) ? g_w0h : (MODE == 1) ? g_w1h : g_w2h;
    const __nv_bfloat16* Bl = (MODE == 0) ? g_w0l : (MODE == 1) ? g_w1l : g_w2l;
    const char* bgh = (const char*)(Bh + ((size_t)e * NN + n0 + row_i) * KD) + coff;
    const char* bgl = (const char*)(Bl + ((size_t)e * NN + n0 + row_i) * KD) + coff;
    const uint32_t stoff = (uint32_t)(row_i * PITCH + coff);

    const int S = KD / 32;

    auto issue = [&](int s) {
        if (s < S) {
            uint32_t d = sb + (uint32_t)(s % 3) * STG_BYTES + stoff;
            size_t go = (size_t)s * 64;
            cpa16(d, agh + go);
            cpa16(d + 16, agh + go + 16);
            cpa16(d + 10240, agl + go);
            cpa16(d + 10256, agl + go + 16);
            cpa16(d + 20480, bgh + go);
            cpa16(d + 20496, bgh + go + 16);
            cpa16(d + 30720, bgl + go);
            cpa16(d + 30736, bgl + go + 16);
        }
        cpa_commit();
    };

    // ---- ldmatrix offsets within a stage buffer
    const uint32_t a_ld = (uint32_t)((wm * 64 + (lane & 15)) * PITCH +
                                     ((lane >> 4) * 8) * 2);
    const uint32_t b_ld = (uint32_t)((wn * 32 + (lane & 7) + ((lane >> 4) & 1) * 8) * PITCH +
                                     (((lane >> 3) & 1) * 8) * 2);

    float acc[4][4][4];
#pragma unroll
    for (int i = 0; i < 4; i++)
#pragma unroll
        for (int j = 0; j < 4; j++)
#pragma unroll
            for (int q = 0; q < 4; q++) acc[i][j][q] = 0.f;

    issue(0);
    issue(1);

    for (int s = 0; s < S; s++) {
        cpa_wait1();
        __syncthreads();
        const uint32_t bb = sb + (uint32_t)(s % 3) * STG_BYTES;
#pragma unroll
        for (int ks = 0; ks < 2; ks++) {
            const uint32_t ko = (uint32_t)(ks * 32);
            uint32_t ah[4][4], al[4][4], bh[2][4], bl[2][4];
#pragma unroll
            for (int mf = 0; mf < 4; mf++) {
                ldsm4(ah[mf], bb + a_ld + (uint32_t)(mf * 16 * PITCH) + ko);
                ldsm4(al[mf], bb + 10240 + a_ld + (uint32_t)(mf * 16 * PITCH) + ko);
            }
#pragma unroll
            for (int p = 0; p < 2; p++) {
                ldsm4(bh[p], bb + 20480 + b_ld + (uint32_t)(p * 16 * PITCH) + ko);
                ldsm4(bl[p], bb + 30720 + b_ld + (uint32_t)(p * 16 * PITCH) + ko);
            }
#pragma unroll
            for (int mf = 0; mf < 4; mf++)
#pragma unroll
                for (int p = 0; p < 2; p++)
#pragma unroll
                    for (int sub = 0; sub < 2; sub++) {
                        int nf = p * 2 + sub;
                        mma16816(acc[mf][nf], ah[mf], bh[p][2 * sub], bh[p][2 * sub + 1]);
                        mma16816(acc[mf][nf], ah[mf], bl[p][2 * sub], bl[p][2 * sub + 1]);
                        mma16816(acc[mf][nf], al[mf], bh[p][2 * sub], bh[p][2 * sub + 1]);
                    }
        }
        issue(s + 2);
    }

    // ---- epilogue -----------------------------------------------------------
    const float* bias = biasall + (size_t)e * NN + n0;
#pragma unroll
    for (int mf = 0; mf < 4; mf++) {
        int mbase = wm * 64 + mf * 16 + (lane >> 2);
#pragma unroll
        for (int half = 0; half < 2; half++) {
            int m = mbase + half * 8;
            if (m >= vend) continue;
            size_t r = (size_t)(r0 + m);
#pragma unroll
            for (int nf = 0; nf < 4; nf++) {
                int col = wn * 32 + nf * 8 + (lane & 3) * 2;
                float c0 = acc[mf][nf][2 * half + 0] + bias[col];
                float c1 = acc[mf][nf][2 * half + 1] + bias[col + 1];
                if (MODE == 2) {
                    *(float2*)(g_y + r * DM + n0 + col) = make_float2(c0, c1);
                } else if (MODE == 0) {
                    *(float2*)(g_act + r * DH + n0 + col) = make_float2(c0, c1);
                } else {
                    float2 h = *(const float2*)(g_act + r * DH + n0 + col);
                    float v0 = h.x * (c0 / (1.f + expf(-c0)));
                    float v1 = h.y * (c1 / (1.f + expf(-c1)));
                    uint32_t hi2, lo2;
                    cvt2(v0, v1, hi2, lo2);
                    *(uint32_t*)(g_acth + r * DH + n0 + col) = hi2;
                    *(uint32_t*)(g_actl + r * DH + n0 + col) = lo2;
                }
            }
        }
    }
}

// ----- combine -------------------------------------------------------------
__global__ void combine_kernel(float* __restrict__ out) {
    int t = blockIdx.x;
    int d4 = threadIdx.x;
    int r0 = g_tokrow[2 * t + 0];
    int r1 = g_tokrow[2 * t + 1];
    float w0 = g_tokw[2 * t + 0];
    float w1 = g_tokw[2 * t + 1];
    const float4 y0 = *(const float4*)(g_y + (size_t)r0 * DM + d4 * 4);
    const float4 y1 = *(const float4*)(g_y + (size_t)r1 * DM + d4 * 4);
    float4 o;
    o.x = w0 * y0.x + w1 * y1.x;
    o.y = w0 * y0.y + w1 * y1.y;
    o.z = w0 * y0.z + w1 * y1.z;
    o.w = w0 * y0.w + w1 * y1.w;
    *(float4*)(out + (size_t)t * DM + d4 * 4) = o;
}

// ---------------------------------------------------------------------------
extern "C" void kernel_launch(void* const* d_in, const int* in_sizes, int n_in,
                              void* d_out, int out_size) {
    (void)in_sizes; (void)n_in; (void)out_size;
    const float* x  = (const float*)d_in[0];
    const float* Wg = (const float*)d_in[1];
    const float* bg = (const float*)d_in[2];
    const float* W0 = (const float*)d_in[3];
    const float* b0 = (const float*)d_in[4];
    const float* W1 = (const float*)d_in[5];
    const float* b1 = (const float*)d_in[6];
    const float* W2 = (const float*)d_in[7];
    const float* b2 = (const float*)d_in[8];
    float* out = (float*)d_out;

    cudaFuncSetAttribute(moe_gemm_mma<0>,
                         cudaFuncAttributeMaxDynamicSharedMemorySize, SMEM_DYN);
    cudaFuncSetAttribute(moe_gemm_mma<1>,
                         cudaFuncAttributeMaxDynamicSharedMemorySize, SMEM_DYN);
    cudaFuncSetAttribute(moe_gemm_mma<2>,
                         cudaFuncAttributeMaxDynamicSharedMemorySize, SMEM_DYN);

    convert_x_kernel<<<T_TOKENS * DM / (256 * 4), 256>>>(x);

    dim3 tb(32, 8);
    transpose_convert<0><<<dim3(DH / 32, DM / 32, NE), tb>>>(W0);
    transpose_convert<1><<<dim3(DH / 32, DM / 32, NE), tb>>>(W1);
    transpose_convert<2><<<dim3(DM / 32, DH / 32, NE), tb>>>(W2);

    routing_kernel<<<T_TOKENS / 8, 256>>>(x, Wg, bg);
    prefix_kernel<<<1, 32>>>();
    scatter_kernel<<<T_TOKENS / 256, 256>>>();

    moe_gemm_mma<0><<<dim3(DH / 128, NROWS / 128), 256, SMEM_DYN>>>(b0);
    moe_gemm_mma<1><<<dim3(DH / 128, NROWS / 128), 256, SMEM_DYN>>>(b1);
    moe_gemm_mma<2><<<dim3(DM / 128, NROWS / 128), 256, SMEM_DYN>>>(b2);

    combine_kernel<<<T_TOKENS, 256>>>(out);
}

// round 9
// speedup vs baseline: 3.7888x; 1.6387x over previous
#include <cuda_runtime.h>
#include <cuda_fp16.h>
#include <math.h>
#include <stdint.h>

// ---------------------------------------------------------------------------
// MoE FFN (top-2 of 8, d_model=1024, d_hid=4096, T=4096), mma.sync fp16 path.
//
//   convert_x (+zero): x fp32 -> g_xh/g_xl fp16 hi + residual lo
//   transpose_convert x3: W fp32 [E][K][N] -> fp16 [E][N][K]
//   routing / prefix / scatter
//   moe_gemm<0>: u0 = Xg @ W0 + b0          (fp32 out)
//   moe_gemm<1>: act = u0 * silu(Xg@W1+b1)  (fp16 hi/lo out)
//   moe_gemm<2>: y   = act @ W2 + b2
//   combine
//
// 2-term fp16 split (Ahi*B + Alo*B, B single fp16): A pair ~22-bit exact,
// output error dominated by fp16 weight quantization (~1.5e-4 rel).
// CTA tile 128x128, BK=32, 8 warps (2Mx4N), cp.async 3-stage ring,
// 80B smem pitch, stage = Ahi(10240)+Alo(10240)+B(10240) = 30720 B.
// ---------------------------------------------------------------------------

#define T_TOKENS 4096
#define DM 1024
#define DH 4096
#define NE 8
#define NROWS 9216

// ----- scratch -------------------------------------------------------------
__device__ float  g_act[(size_t)NROWS * DH];      // u0 (fp32, gemm0 -> gemm1)
__device__ __half g_acth[(size_t)NROWS * DH];     // act hi (gemm1 -> gemm2)
__device__ __half g_actl[(size_t)NROWS * DH];     // act lo
__device__ float  g_y[(size_t)NROWS * DM];
__device__ __half g_xh[(size_t)T_TOKENS * DM];
__device__ __half g_xl[(size_t)T_TOKENS * DM];
__device__ int    g_perm[NROWS];
__device__ int    g_tokrow[T_TOKENS * 2];
__device__ float  g_tokw[T_TOKENS * 2];
__device__ int    g_tokexp[T_TOKENS * 2];
__device__ int    g_cnt[NE];
__device__ int    g_run[NE];
__device__ int    g_abase[NE + 1];

__device__ __half g_w0[(size_t)NE * DH * DM];   // [E][N][K] fp16
__device__ __half g_w1[(size_t)NE * DH * DM];
__device__ __half g_w2[(size_t)NE * DM * DH];

// ----- helpers -------------------------------------------------------------
__device__ __forceinline__ uint32_t s2u(const void* p) {
    uint32_t a;
    asm("{ .reg .u64 t; cvta.to.shared.u64 t, %1; cvt.u32.u64 %0, t; }"
        : "=r"(a) : "l"(p));
    return a;
}
// f -> fp16 hi (RN) + fp16 lo (RN of exact residual), packed x2
__device__ __forceinline__ void cvtf16(float f0, float f1, uint32_t& hi2, uint32_t& lo2) {
    __half h0 = __float2half_rn(f0), h1 = __float2half_rn(f1);
    float r0 = f0 - __half2float(h0);
    float r1 = f1 - __half2float(h1);
    __half2 H = __halves2half2(h0, h1);
    __half2 L = __floats2half2_rn(r0, r1);
    hi2 = *(uint32_t*)&H;
    lo2 = *(uint32_t*)&L;
}
__device__ __forceinline__ void ldsm4(uint32_t* r, uint32_t addr) {
    asm volatile("ldmatrix.sync.aligned.m8n8.x4.shared.b16 {%0,%1,%2,%3}, [%4];"
                 : "=r"(r[0]), "=r"(r[1]), "=r"(r[2]), "=r"(r[3]) : "r"(addr));
}
__device__ __forceinline__ void mma16816(float* c, const uint32_t* a,
                                         uint32_t b0, uint32_t b1) {
    asm volatile(
        "mma.sync.aligned.m16n8k16.row.col.f32.f16.f16.f32 "
        "{%0,%1,%2,%3}, {%4,%5,%6,%7}, {%8,%9}, {%0,%1,%2,%3};"
        : "+f"(c[0]), "+f"(c[1]), "+f"(c[2]), "+f"(c[3])
        : "r"(a[0]), "r"(a[1]), "r"(a[2]), "r"(a[3]), "r"(b0), "r"(b1));
}
__device__ __forceinline__ void cpa16(uint32_t d, const void* g) {
    asm volatile("cp.async.cg.shared.global [%0], [%1], 16;" :: "r"(d), "l"(g));
}
__device__ __forceinline__ void cpa_commit() {
    asm volatile("cp.async.commit_group;" ::: "memory");
}
__device__ __forceinline__ void cpa_wait1() {
    asm volatile("cp.async.wait_group 1;" ::: "memory");
}

// ----- convert_x (+ counter zero) ------------------------------------------
__global__ void convert_x_kernel(const float* __restrict__ x) {
    if (blockIdx.x == 0 && threadIdx.x < NE) g_cnt[threadIdx.x] = 0;
    size_t i = ((size_t)blockIdx.x * blockDim.x + threadIdx.x) * 4;
    if (i >= (size_t)T_TOKENS * DM) return;
    float4 v = *(const float4*)(x + i);
    uint32_t h0, l0, h1, l1;
    cvtf16(v.x, v.y, h0, l0);
    cvtf16(v.z, v.w, h1, l1);
    *(uint2*)(g_xh + i) = make_uint2(h0, h1);
    *(uint2*)(g_xl + i) = make_uint2(l0, l1);
}

// ----- routing (one warp per token) ----------------------------------------
__global__ void routing_kernel(const float* __restrict__ x,
                               const float* __restrict__ Wg,
                               const float* __restrict__ bg) {
    int warp = (blockIdx.x * blockDim.x + threadIdx.x) >> 5;
    int lane = threadIdx.x & 31;
    if (warp >= T_TOKENS) return;
    const float* xr = x + (size_t)warp * DM;

    float acc[8];
#pragma unroll
    for (int e = 0; e < 8; e++) acc[e] = 0.f;
    for (int d = lane; d < DM; d += 32) {
        float xv = xr[d];
        const float4* wp = (const float4*)(Wg + (size_t)d * 8);
        float4 wa = wp[0];
        float4 wb = wp[1];
        acc[0] += xv * wa.x; acc[1] += xv * wa.y;
        acc[2] += xv * wa.z; acc[3] += xv * wa.w;
        acc[4] += xv * wb.x; acc[5] += xv * wb.y;
        acc[6] += xv * wb.z; acc[7] += xv * wb.w;
    }
#pragma unroll
    for (int e = 0; e < 8; e++) {
        float v = acc[e];
        for (int o = 16; o; o >>= 1) v += __shfl_xor_sync(0xffffffffu, v, o);
        acc[e] = v;
    }
    if (lane == 0) {
        float lg[8];
#pragma unroll
        for (int e = 0; e < 8; e++) lg[e] = acc[e] + bg[e];
        float v0 = lg[0]; int i0 = 0;
#pragma unroll
        for (int e = 1; e < 8; e++) if (lg[e] > v0) { v0 = lg[e]; i0 = e; }
        float v1 = -3.4e38f; int i1 = -1;
#pragma unroll
        for (int e = 0; e < 8; e++)
            if (e != i0 && lg[e] > v1) { v1 = lg[e]; i1 = e; }
        float e1 = expf(v1 - v0);
        float w0 = 1.f / (1.f + e1);
        float w1 = e1 / (1.f + e1);
        int t = warp;
        g_tokexp[2 * t + 0] = i0;
        g_tokexp[2 * t + 1] = i1;
        g_tokw[2 * t + 0] = w0;
        g_tokw[2 * t + 1] = w1;
        atomicAdd(&g_cnt[i0], 1);
        atomicAdd(&g_cnt[i1], 1);
    }
}

// ----- prefix / scatter ----------------------------------------------------
__global__ void prefix_kernel() {
    if (threadIdx.x == 0) {
        int s = 0;
        for (int e = 0; e < NE; e++) {
            g_abase[e] = s;
            g_run[e] = s;
            s += (g_cnt[e] + 127) & ~127;
        }
        g_abase[NE] = s;
    }
}
__global__ void scatter_kernel() {
    int t = blockIdx.x * blockDim.x + threadIdx.x;
    if (t >= T_TOKENS) return;
#pragma unroll
    for (int k = 0; k < 2; k++) {
        int e = g_tokexp[2 * t + k];
        int pos = atomicAdd(&g_run[e], 1);
        g_perm[pos] = t;
        g_tokrow[2 * t + k] = pos;
    }
}

// ----- transpose + convert W[e][K][N] fp32 -> [e][N][K] fp16 ---------------
template <int WHICH>
__global__ void transpose_convert(const float* __restrict__ W) {
    const int K = (WHICH == 2) ? DH : DM;
    const int N = (WHICH == 2) ? DM : DH;
    __half* oh = (WHICH == 0) ? g_w0 : (WHICH == 1) ? g_w1 : g_w2;
    __shared__ float tile[32][33];
    int e = blockIdx.z;
    int n0 = blockIdx.x * 32, k0 = blockIdx.y * 32;
    int tx = threadIdx.x, ty = threadIdx.y;  // 32 x 8
    const float* src = W + ((size_t)e * K + k0) * N + n0 + tx;
#pragma unroll
    for (int i = 0; i < 4; i++)
        tile[ty + 8 * i][tx] = src[(size_t)(ty + 8 * i) * N];
    __syncthreads();
    size_t ob = ((size_t)e * N + n0) * K + k0 + tx;
#pragma unroll
    for (int i = 0; i < 4; i++) {
        int nl = ty + 8 * i;
        oh[ob + (size_t)nl * K] = __float2half_rn(tile[tx][nl]);
    }
}

// ----- HMMA grouped GEMM (cp.async 3-stage ring, fp16 2-term) --------------
// Stage (30720 B): Ahi[0) Alo[10240) B[20480); 80 B row pitch.
#define STG_BYTES 30720
#define PITCH 80
#define SMEM_DYN (3 * STG_BYTES)

template <int MODE>
__global__ void __launch_bounds__(256, 2)
moe_gemm_mma(const float* __restrict__ biasall) {
    const int KD = (MODE == 2) ? DH : DM;
    const int NN = (MODE == 2) ? DM : DH;

    const int r0 = blockIdx.y * 128;
    if (r0 >= g_abase[NE]) return;
    int e = 0;
    while (e < NE - 1 && r0 >= g_abase[e + 1]) e++;
    int vend = g_abase[e] + g_cnt[e] - r0;
    if (vend <= 0) return;
    if (vend > 128) vend = 128;
    const int n0 = blockIdx.x * 128;

    extern __shared__ char smem_raw[];
    const uint32_t sb = s2u(smem_raw);

    const int tid = threadIdx.x;
    const int w = tid >> 5;
    const int lane = tid & 31;
    const int wm = w & 1;
    const int wn = w >> 1;

    // ---- cp.async mapping: 2 threads per tile row, 32B each
    const int row_i = tid >> 1;
    const int coff = (tid & 1) * 32;
    const char* agh;
    const char* agl;
    if (MODE == 2) {
        agh = (const char*)(g_acth + (size_t)(r0 + row_i) * DH) + coff;
        agl = (const char*)(g_actl + (size_t)(r0 + row_i) * DH) + coff;
    } else {
        size_t t = (size_t)g_perm[r0 + row_i];
        agh = (const char*)(g_xh + t * DM) + coff;
        agl = (const char*)(g_xl + t * DM) + coff;
    }
    const __half* B = (MODE == 0) ? g_w0 : (MODE == 1) ? g_w1 : g_w2;
    const char* bg = (const char*)(B + ((size_t)e * NN + n0 + row_i) * KD) + coff;
    const uint32_t stoff = (uint32_t)(row_i * PITCH + coff);

    const int S = KD / 32;

    auto issue = [&](int s) {
        if (s < S) {
            uint32_t d = sb + (uint32_t)(s % 3) * STG_BYTES + stoff;
            size_t go = (size_t)s * 64;
            cpa16(d, agh + go);
            cpa16(d + 16, agh + go + 16);
            cpa16(d + 10240, agl + go);
            cpa16(d + 10256, agl + go + 16);
            cpa16(d + 20480, bg + go);
            cpa16(d + 20496, bg + go + 16);
        }
        cpa_commit();
    };

    // ---- ldmatrix offsets within a stage buffer
    const uint32_t a_ld = (uint32_t)((wm * 64 + (lane & 15)) * PITCH +
                                     ((lane >> 4) * 8) * 2);
    const uint32_t b_ld = (uint32_t)((wn * 32 + (lane & 7) + ((lane >> 4) & 1) * 8) * PITCH +
                                     (((lane >> 3) & 1) * 8) * 2);

    float acc[4][4][4];
#pragma unroll
    for (int i = 0; i < 4; i++)
#pragma unroll
        for (int j = 0; j < 4; j++)
#pragma unroll
            for (int q = 0; q < 4; q++) acc[i][j][q] = 0.f;

    issue(0);
    issue(1);

    for (int s = 0; s < S; s++) {
        cpa_wait1();
        __syncthreads();
        const uint32_t bb = sb + (uint32_t)(s % 3) * STG_BYTES;
#pragma unroll
        for (int ks = 0; ks < 2; ks++) {
            const uint32_t ko = (uint32_t)(ks * 32);
            uint32_t ah[4][4], al[4][4], bh[2][4];
#pragma unroll
            for (int mf = 0; mf < 4; mf++) {
                ldsm4(ah[mf], bb + a_ld + (uint32_t)(mf * 16 * PITCH) + ko);
                ldsm4(al[mf], bb + 10240 + a_ld + (uint32_t)(mf * 16 * PITCH) + ko);
            }
#pragma unroll
            for (int p = 0; p < 2; p++)
                ldsm4(bh[p], bb + 20480 + b_ld + (uint32_t)(p * 16 * PITCH) + ko);
#pragma unroll
            for (int mf = 0; mf < 4; mf++)
#pragma unroll
                for (int p = 0; p < 2; p++)
#pragma unroll
                    for (int sub = 0; sub < 2; sub++) {
                        int nf = p * 2 + sub;
                        mma16816(acc[mf][nf], ah[mf], bh[p][2 * sub], bh[p][2 * sub + 1]);
                        mma16816(acc[mf][nf], al[mf], bh[p][2 * sub], bh[p][2 * sub + 1]);
                    }
        }
        issue(s + 2);
    }

    // ---- epilogue -----------------------------------------------------------
    const float* bias = biasall + (size_t)e * NN + n0;
#pragma unroll
    for (int mf = 0; mf < 4; mf++) {
        int mbase = wm * 64 + mf * 16 + (lane >> 2);
#pragma unroll
        for (int half = 0; half < 2; half++) {
            int m = mbase + half * 8;
            if (m >= vend) continue;
            size_t r = (size_t)(r0 + m);
#pragma unroll
            for (int nf = 0; nf < 4; nf++) {
                int col = wn * 32 + nf * 8 + (lane & 3) * 2;
                float c0 = acc[mf][nf][2 * half + 0] + bias[col];
                float c1 = acc[mf][nf][2 * half + 1] + bias[col + 1];
                if (MODE == 2) {
                    *(float2*)(g_y + r * DM + n0 + col) = make_float2(c0, c1);
                } else if (MODE == 0) {
                    *(float2*)(g_act + r * DH + n0 + col) = make_float2(c0, c1);
                } else {
                    float2 h = *(const float2*)(g_act + r * DH + n0 + col);
                    float v0 = h.x * (c0 / (1.f + expf(-c0)));
                    float v1 = h.y * (c1 / (1.f + expf(-c1)));
                    uint32_t hi2, lo2;
                    cvtf16(v0, v1, hi2, lo2);
                    *(uint32_t*)(g_acth + r * DH + n0 + col) = hi2;
                    *(uint32_t*)(g_actl + r * DH + n0 + col) = lo2;
                }
            }
        }
    }
}

// ----- combine -------------------------------------------------------------
__global__ void combine_kernel(float* __restrict__ out) {
    int t = blockIdx.x;
    int d4 = threadIdx.x;
    int r0 = g_tokrow[2 * t + 0];
    int r1 = g_tokrow[2 * t + 1];
    float w0 = g_tokw[2 * t + 0];
    float w1 = g_tokw[2 * t + 1];
    const float4 y0 = *(const float4*)(g_y + (size_t)r0 * DM + d4 * 4);
    const float4 y1 = *(const float4*)(g_y + (size_t)r1 * DM + d4 * 4);
    float4 o;
    o.x = w0 * y0.x + w1 * y1.x;
    o.y = w0 * y0.y + w1 * y1.y;
    o.z = w0 * y0.z + w1 * y1.z;
    o.w = w0 * y0.w + w1 * y1.w;
    *(float4*)(out + (size_t)t * DM + d4 * 4) = o;
}

// ---------------------------------------------------------------------------
extern "C" void kernel_launch(void* const* d_in, const int* in_sizes, int n_in,
                              void* d_out, int out_size) {
    (void)in_sizes; (void)n_in; (void)out_size;
    const float* x  = (const float*)d_in[0];
    const float* Wg = (const float*)d_in[1];
    const float* bg = (const float*)d_in[2];
    const float* W0 = (const float*)d_in[3];
    const float* b0 = (const float*)d_in[4];
    const float* W1 = (const float*)d_in[5];
    const float* b1 = (const float*)d_in[6];
    const float* W2 = (const float*)d_in[7];
    const float* b2 = (const float*)d_in[8];
    float* out = (float*)d_out;

    cudaFuncSetAttribute(moe_gemm_mma<0>,
                         cudaFuncAttributeMaxDynamicSharedMemorySize, SMEM_DYN);
    cudaFuncSetAttribute(moe_gemm_mma<1>,
                         cudaFuncAttributeMaxDynamicSharedMemorySize, SMEM_DYN);
    cudaFuncSetAttribute(moe_gemm_mma<2>,
                         cudaFuncAttributeMaxDynamicSharedMemorySize, SMEM_DYN);

    convert_x_kernel<<<T_TOKENS * DM / (256 * 4), 256>>>(x);

    dim3 tb(32, 8);
    transpose_convert<0><<<dim3(DH / 32, DM / 32, NE), tb>>>(W0);
    transpose_convert<1><<<dim3(DH / 32, DM / 32, NE), tb>>>(W1);
    transpose_convert<2><<<dim3(DM / 32, DH / 32, NE), tb>>>(W2);

    routing_kernel<<<T_TOKENS / 8, 256>>>(x, Wg, bg);
    prefix_kernel<<<1, 32>>>();
    scatter_kernel<<<T_TOKENS / 256, 256>>>();

    moe_gemm_mma<0><<<dim3(DH / 128, NROWS / 128), 256, SMEM_DYN>>>(b0);
    moe_gemm_mma<1><<<dim3(DH / 128, NROWS / 128), 256, SMEM_DYN>>>(b1);
    moe_gemm_mma<2><<<dim3(DM / 128, NROWS / 128), 256, SMEM_DYN>>>(b2);

    combine_kernel<<<T_TOKENS, 256>>>(out);
}

// round 11
// speedup vs baseline: 5.4946x; 1.4502x over previous
#include <cuda_runtime.h>
#include <cuda_fp16.h>
#include <math.h>
#include <stdint.h>

// ---------------------------------------------------------------------------
// MoE FFN (top-2 of 8, d_model=1024, d_hid=4096, T=4096), mma.sync fp16 path.
//
//   convert_x (+zero): x fp32 -> g_xh fp16
//   transpose_convert x3: W fp32 [E][K][N] -> fp16 [E][N][K]
//   routing / prefix / scatter
//   moe_gemm<0>: u0 = Xg @ W0 + b0          (fp32 out)
//   moe_gemm<1>: act = u0 * silu(Xg@W1+b1)  (fp16 out)
//   moe_gemm<2>: y   = act @ W2 + b2
//   combine
//
// Single-term fp16 x fp16 HMMA (fp32 acc). Calibrated error model:
// ~2.1e-4 rms per quantized operand per GEMM, 6 sources -> ~5e-4 total.
// CTA tile 128x128, BK=32, 8 warps (2Mx4N), cp.async 4-stage ring
// (wait_group 2), 80B smem pitch, stage = A(10240)+B(10240) = 20480 B.
// ---------------------------------------------------------------------------

#define T_TOKENS 4096
#define DM 1024
#define DH 4096
#define NE 8
#define NROWS 9216

// ----- scratch -------------------------------------------------------------
__device__ float  g_act[(size_t)NROWS * DH];      // u0 (fp32, gemm0 -> gemm1)
__device__ __half g_acth[(size_t)NROWS * DH];     // act (fp16, gemm1 -> gemm2)
__device__ float  g_y[(size_t)NROWS * DM];
__device__ __half g_xh[(size_t)T_TOKENS * DM];
__device__ int    g_perm[NROWS];
__device__ int    g_tokrow[T_TOKENS * 2];
__device__ float  g_tokw[T_TOKENS * 2];
__device__ int    g_tokexp[T_TOKENS * 2];
__device__ int    g_cnt[NE];
__device__ int    g_run[NE];
__device__ int    g_abase[NE + 1];

__device__ __half g_w0[(size_t)NE * DH * DM];   // [E][N][K] fp16
__device__ __half g_w1[(size_t)NE * DH * DM];
__device__ __half g_w2[(size_t)NE * DM * DH];

// ----- helpers -------------------------------------------------------------
__device__ __forceinline__ uint32_t s2u(const void* p) {
    uint32_t a;
    asm("{ .reg .u64 t; cvta.to.shared.u64 t, %1; cvt.u32.u64 %0, t; }"
        : "=r"(a) : "l"(p));
    return a;
}
__device__ __forceinline__ void ldsm4(uint32_t* r, uint32_t addr) {
    asm volatile("ldmatrix.sync.aligned.m8n8.x4.shared.b16 {%0,%1,%2,%3}, [%4];"
                 : "=r"(r[0]), "=r"(r[1]), "=r"(r[2]), "=r"(r[3]) : "r"(addr));
}
__device__ __forceinline__ void mma16816(float* c, const uint32_t* a,
                                         uint32_t b0, uint32_t b1) {
    asm volatile(
        "mma.sync.aligned.m16n8k16.row.col.f32.f16.f16.f32 "
        "{%0,%1,%2,%3}, {%4,%5,%6,%7}, {%8,%9}, {%0,%1,%2,%3};"
        : "+f"(c[0]), "+f"(c[1]), "+f"(c[2]), "+f"(c[3])
        : "r"(a[0]), "r"(a[1]), "r"(a[2]), "r"(a[3]), "r"(b0), "r"(b1));
}
__device__ __forceinline__ void cpa16(uint32_t d, const void* g) {
    asm volatile("cp.async.cg.shared.global [%0], [%1], 16;" :: "r"(d), "l"(g));
}
__device__ __forceinline__ void cpa_commit() {
    asm volatile("cp.async.commit_group;" ::: "memory");
}
__device__ __forceinline__ void cpa_wait2() {
    asm volatile("cp.async.wait_group 2;" ::: "memory");
}

// ----- convert_x (+ counter zero) ------------------------------------------
__global__ void convert_x_kernel(const float* __restrict__ x) {
    if (blockIdx.x == 0 && threadIdx.x < NE) g_cnt[threadIdx.x] = 0;
    size_t i = ((size_t)blockIdx.x * blockDim.x + threadIdx.x) * 4;
    if (i >= (size_t)T_TOKENS * DM) return;
    float4 v = *(const float4*)(x + i);
    __half2 h0 = __floats2half2_rn(v.x, v.y);
    __half2 h1 = __floats2half2_rn(v.z, v.w);
    *(uint2*)(g_xh + i) = make_uint2(*(uint32_t*)&h0, *(uint32_t*)&h1);
}

// ----- routing (one warp per token) ----------------------------------------
__global__ void routing_kernel(const float* __restrict__ x,
                               const float* __restrict__ Wg,
                               const float* __restrict__ bg) {
    int warp = (blockIdx.x * blockDim.x + threadIdx.x) >> 5;
    int lane = threadIdx.x & 31;
    if (warp >= T_TOKENS) return;
    const float* xr = x + (size_t)warp * DM;

    float acc[8];
#pragma unroll
    for (int e = 0; e < 8; e++) acc[e] = 0.f;
    for (int d = lane; d < DM; d += 32) {
        float xv = xr[d];
        const float4* wp = (const float4*)(Wg + (size_t)d * 8);
        float4 wa = wp[0];
        float4 wb = wp[1];
        acc[0] += xv * wa.x; acc[1] += xv * wa.y;
        acc[2] += xv * wa.z; acc[3] += xv * wa.w;
        acc[4] += xv * wb.x; acc[5] += xv * wb.y;
        acc[6] += xv * wb.z; acc[7] += xv * wb.w;
    }
#pragma unroll
    for (int e = 0; e < 8; e++) {
        float v = acc[e];
        for (int o = 16; o; o >>= 1) v += __shfl_xor_sync(0xffffffffu, v, o);
        acc[e] = v;
    }
    if (lane == 0) {
        float lg[8];
#pragma unroll
        for (int e = 0; e < 8; e++) lg[e] = acc[e] + bg[e];
        float v0 = lg[0]; int i0 = 0;
#pragma unroll
        for (int e = 1; e < 8; e++) if (lg[e] > v0) { v0 = lg[e]; i0 = e; }
        float v1 = -3.4e38f; int i1 = -1;
#pragma unroll
        for (int e = 0; e < 8; e++)
            if (e != i0 && lg[e] > v1) { v1 = lg[e]; i1 = e; }
        float e1 = expf(v1 - v0);
        float w0 = 1.f / (1.f + e1);
        float w1 = e1 / (1.f + e1);
        int t = warp;
        g_tokexp[2 * t + 0] = i0;
        g_tokexp[2 * t + 1] = i1;
        g_tokw[2 * t + 0] = w0;
        g_tokw[2 * t + 1] = w1;
        atomicAdd(&g_cnt[i0], 1);
        atomicAdd(&g_cnt[i1], 1);
    }
}

// ----- prefix / scatter ----------------------------------------------------
__global__ void prefix_kernel() {
    if (threadIdx.x == 0) {
        int s = 0;
        for (int e = 0; e < NE; e++) {
            g_abase[e] = s;
            g_run[e] = s;
            s += (g_cnt[e] + 127) & ~127;
        }
        g_abase[NE] = s;
    }
}
__global__ void scatter_kernel() {
    int t = blockIdx.x * blockDim.x + threadIdx.x;
    if (t >= T_TOKENS) return;
#pragma unroll
    for (int k = 0; k < 2; k++) {
        int e = g_tokexp[2 * t + k];
        int pos = atomicAdd(&g_run[e], 1);
        g_perm[pos] = t;
        g_tokrow[2 * t + k] = pos;
    }
}

// ----- transpose + convert W[e][K][N] fp32 -> [e][N][K] fp16 ---------------
template <int WHICH>
__global__ void transpose_convert(const float* __restrict__ W) {
    const int K = (WHICH == 2) ? DH : DM;
    const int N = (WHICH == 2) ? DM : DH;
    __half* oh = (WHICH == 0) ? g_w0 : (WHICH == 1) ? g_w1 : g_w2;
    __shared__ float tile[32][33];
    int e = blockIdx.z;
    int n0 = blockIdx.x * 32, k0 = blockIdx.y * 32;
    int tx = threadIdx.x, ty = threadIdx.y;  // 32 x 8
    const float* src = W + ((size_t)e * K + k0) * N + n0 + tx;
#pragma unroll
    for (int i = 0; i < 4; i++)
        tile[ty + 8 * i][tx] = src[(size_t)(ty + 8 * i) * N];
    __syncthreads();
    size_t ob = ((size_t)e * N + n0) * K + k0 + tx;
#pragma unroll
    for (int i = 0; i < 4; i++) {
        int nl = ty + 8 * i;
        oh[ob + (size_t)nl * K] = __float2half_rn(tile[tx][nl]);
    }
}

// ----- HMMA grouped GEMM (cp.async 4-stage ring, single-term fp16) ---------
// Stage (20480 B): A[0) B[10240); 80 B row pitch.
#define STG_BYTES 20480
#define PITCH 80
#define SMEM_DYN (4 * STG_BYTES)

template <int MODE>
__global__ void __launch_bounds__(256, 2)
moe_gemm_mma(const float* __restrict__ biasall) {
    const int KD = (MODE == 2) ? DH : DM;
    const int NN = (MODE == 2) ? DM : DH;

    const int r0 = blockIdx.y * 128;
    if (r0 >= g_abase[NE]) return;
    int e = 0;
    while (e < NE - 1 && r0 >= g_abase[e + 1]) e++;
    int vend = g_abase[e] + g_cnt[e] - r0;
    if (vend <= 0) return;
    if (vend > 128) vend = 128;
    const int n0 = blockIdx.x * 128;

    extern __shared__ char smem_raw[];
    const uint32_t sb = s2u(smem_raw);

    const int tid = threadIdx.x;
    const int w = tid >> 5;
    const int lane = tid & 31;
    const int wm = w & 1;
    const int wn = w >> 1;

    // ---- cp.async mapping: 2 threads per tile row, 32B each
    const int row_i = tid >> 1;
    const int coff = (tid & 1) * 32;
    const char* ag;
    if (MODE == 2) {
        ag = (const char*)(g_acth + (size_t)(r0 + row_i) * DH) + coff;
    } else {
        size_t t = (size_t)g_perm[r0 + row_i];
        ag = (const char*)(g_xh + t * DM) + coff;
    }
    const __half* B = (MODE == 0) ? g_w0 : (MODE == 1) ? g_w1 : g_w2;
    const char* bg = (const char*)(B + ((size_t)e * NN + n0 + row_i) * KD) + coff;
    const uint32_t stoff = (uint32_t)(row_i * PITCH + coff);

    const int S = KD / 32;

    auto issue = [&](int s) {
        if (s < S) {
            uint32_t d = sb + (uint32_t)(s & 3) * STG_BYTES + stoff;
            size_t go = (size_t)s * 64;
            cpa16(d, ag + go);
            cpa16(d + 16, ag + go + 16);
            cpa16(d + 10240, bg + go);
            cpa16(d + 10256, bg + go + 16);
        }
        cpa_commit();
    };

    // ---- ldmatrix offsets within a stage buffer
    const uint32_t a_ld = (uint32_t)((wm * 64 + (lane & 15)) * PITCH +
                                     ((lane >> 4) * 8) * 2);
    const uint32_t b_ld = (uint32_t)((wn * 32 + (lane & 7) + ((lane >> 4) & 1) * 8) * PITCH +
                                     (((lane >> 3) & 1) * 8) * 2);

    float acc[4][4][4];
#pragma unroll
    for (int i = 0; i < 4; i++)
#pragma unroll
        for (int j = 0; j < 4; j++)
#pragma unroll
            for (int q = 0; q < 4; q++) acc[i][j][q] = 0.f;

    issue(0);
    issue(1);
    issue(2);

    for (int s = 0; s < S; s++) {
        cpa_wait2();
        __syncthreads();
        const uint32_t bb = sb + (uint32_t)(s & 3) * STG_BYTES;
#pragma unroll
        for (int ks = 0; ks < 2; ks++) {
            const uint32_t ko = (uint32_t)(ks * 32);
            uint32_t ah[4][4], bh[2][4];
#pragma unroll
            for (int mf = 0; mf < 4; mf++)
                ldsm4(ah[mf], bb + a_ld + (uint32_t)(mf * 16 * PITCH) + ko);
#pragma unroll
            for (int p = 0; p < 2; p++)
                ldsm4(bh[p], bb + 10240 + b_ld + (uint32_t)(p * 16 * PITCH) + ko);
#pragma unroll
            for (int mf = 0; mf < 4; mf++)
#pragma unroll
                for (int p = 0; p < 2; p++)
#pragma unroll
                    for (int sub = 0; sub < 2; sub++)
                        mma16816(acc[mf][p * 2 + sub], ah[mf],
                                 bh[p][2 * sub], bh[p][2 * sub + 1]);
        }
        issue(s + 3);
    }

    // ---- epilogue -----------------------------------------------------------
    const float* bias = biasall + (size_t)e * NN + n0;
#pragma unroll
    for (int mf = 0; mf < 4; mf++) {
        int mbase = wm * 64 + mf * 16 + (lane >> 2);
#pragma unroll
        for (int half = 0; half < 2; half++) {
            int m = mbase + half * 8;
            if (m >= vend) continue;
            size_t r = (size_t)(r0 + m);
#pragma unroll
            for (int nf = 0; nf < 4; nf++) {
                int col = wn * 32 + nf * 8 + (lane & 3) * 2;
                float c0 = acc[mf][nf][2 * half + 0] + bias[col];
                float c1 = acc[mf][nf][2 * half + 1] + bias[col + 1];
                if (MODE == 2) {
                    *(float2*)(g_y + r * DM + n0 + col) = make_float2(c0, c1);
                } else if (MODE == 0) {
                    *(float2*)(g_act + r * DH + n0 + col) = make_float2(c0, c1);
                } else {
                    float2 h = *(const float2*)(g_act + r * DH + n0 + col);
                    float v0 = h.x * (c0 / (1.f + expf(-c0)));
                    float v1 = h.y * (c1 / (1.f + expf(-c1)));
                    __half2 hv = __floats2half2_rn(v0, v1);
                    *(uint32_t*)(g_acth + r * DH + n0 + col) = *(uint32_t*)&hv;
                }
            }
        }
    }
}

// ----- combine -------------------------------------------------------------
__global__ void combine_kernel(float* __restrict__ out) {
    int t = blockIdx.x;
    int d4 = threadIdx.x;
    int r0 = g_tokrow[2 * t + 0];
    int r1 = g_tokrow[2 * t + 1];
    float w0 = g_tokw[2 * t + 0];
    float w1 = g_tokw[2 * t + 1];
    const float4 y0 = *(const float4*)(g_y + (size_t)r0 * DM + d4 * 4);
    const float4 y1 = *(const float4*)(g_y + (size_t)r1 * DM + d4 * 4);
    float4 o;
    o.x = w0 * y0.x + w1 * y1.x;
    o.y = w0 * y0.y + w1 * y1.y;
    o.z = w0 * y0.z + w1 * y1.z;
    o.w = w0 * y0.w + w1 * y1.w;
    *(float4*)(out + (size_t)t * DM + d4 * 4) = o;
}

// ---------------------------------------------------------------------------
extern "C" void kernel_launch(void* const* d_in, const int* in_sizes, int n_in,
                              void* d_out, int out_size) {
    (void)in_sizes; (void)n_in; (void)out_size;
    const float* x  = (const float*)d_in[0];
    const float* Wg = (const float*)d_in[1];
    const float* bg = (const float*)d_in[2];
    const float* W0 = (const float*)d_in[3];
    const float* b0 = (const float*)d_in[4];
    const float* W1 = (const float*)d_in[5];
    const float* b1 = (const float*)d_in[6];
    const float* W2 = (const float*)d_in[7];
    const float* b2 = (const float*)d_in[8];
    float* out = (float*)d_out;

    cudaFuncSetAttribute(moe_gemm_mma<0>,
                         cudaFuncAttributeMaxDynamicSharedMemorySize, SMEM_DYN);
    cudaFuncSetAttribute(moe_gemm_mma<1>,
                         cudaFuncAttributeMaxDynamicSharedMemorySize, SMEM_DYN);
    cudaFuncSetAttribute(moe_gemm_mma<2>,
                         cudaFuncAttributeMaxDynamicSharedMemorySize, SMEM_DYN);

    convert_x_kernel<<<T_TOKENS * DM / (256 * 4), 256>>>(x);

    dim3 tb(32, 8);
    transpose_convert<0><<<dim3(DH / 32, DM / 32, NE), tb>>>(W0);
    transpose_convert<1><<<dim3(DH / 32, DM / 32, NE), tb>>>(W1);
    transpose_convert<2><<<dim3(DM / 32, DH / 32, NE), tb>>>(W2);

    routing_kernel<<<T_TOKENS / 8, 256>>>(x, Wg, bg);
    prefix_kernel<<<1, 32>>>();
    scatter_kernel<<<T_TOKENS / 256, 256>>>();

    moe_gemm_mma<0><<<dim3(DH / 128, NROWS / 128), 256, SMEM_DYN>>>(b0);
    moe_gemm_mma<1><<<dim3(DH / 128, NROWS / 128), 256, SMEM_DYN>>>(b1);
    moe_gemm_mma<2><<<dim3(DM / 128, NROWS / 128), 256, SMEM_DYN>>>(b2);

    combine_kernel<<<T_TOKENS, 256>>>(out);
}